// round 15
// baseline (speedup 1.0000x reference)
#include <cuda_runtime.h>

#define Tv 512
#define ROWW 60    // 56 data + 4 pad floats per seq row (240B)
#define MROWW 12   // 8 ints + 4 pad per seq row
#define EFLOATS (64 * ROWW)
#define MINTS   (64 * MROWW)

__device__ float gA[8192 * 8];
__device__ float gU[8192 * 8];
__device__ int   gXF[8192], gXB[8192];
__device__ float gNF[8192], gNB[8192];
__device__ int   gCF[8192], gCB[8192];

typedef unsigned long long u64;

static __device__ __forceinline__ u64 PK(float a, float b) {
    u64 r; asm("mov.b64 %0,{%1,%2};" : "=l"(r) : "r"(__float_as_uint(a)), "r"(__float_as_uint(b))); return r;
}
static __device__ __forceinline__ void UPK(u64 v, float& a, float& b) {
    unsigned x, y; asm("mov.b64 {%0,%1},%2;" : "=r"(x), "=r"(y) : "l"(v));
    a = __uint_as_float(x); b = __uint_as_float(y);
}
static __device__ __forceinline__ u64 FMA2(u64 a, u64 b, u64 c) {
    u64 d; asm("fma.rn.f32x2 %0,%1,%2,%3;" : "=l"(d) : "l"(a), "l"(b), "l"(c)); return d;
}
static __device__ __forceinline__ u64 MUL2(u64 a, u64 b) {
    u64 d; asm("mul.rn.f32x2 %0,%1,%2;" : "=l"(d) : "l"(a), "l"(b)); return d;
}
static __device__ __forceinline__ void cpa16(void* dst, const void* src) {
    unsigned d = (unsigned)__cvta_generic_to_shared(dst);
    asm volatile("cp.async.cg.shared.global [%0], [%1], 16;" :: "r"(d), "l"(src));
}
#define CP_COMMIT() asm volatile("cp.async.commit_group;")
#define CP_WAIT2()  asm volatile("cp.async.wait_group 2;")

#define STAGE(SLOT, MM) do { \
    float* _eb = ES + (SLOT) * EFLOATS; \
    int*   _mb = MS + (SLOT) * MINTS; \
    int*   _lb = LS + (SLOT) * MINTS; \
    _Pragma("unroll") \
    for (int i = 0; i < 28; i++) { \
        int idx = i * 32 + lane; int r = (idx * 4682) >> 16; int c = idx - r * 14; \
        cpa16(_eb + r * ROWW + c * 4, emb + (size_t)r * (Tv * 7) + (MM) * 56 + c * 4); \
    } \
    _Pragma("unroll") \
    for (int i = 0; i < 4; i++) { \
        int idx = i * 32 + lane; int s = idx >> 1; int h = idx & 1; \
        cpa16(_mb + s * MROWW + h * 4, mskb + (size_t)s * Tv + (MM) * 8 + h * 4); \
        cpa16(_lb + s * MROWW + h * 4, labb + (size_t)s * Tv + (MM) * 8 + h * 4); \
    } \
    CP_COMMIT(); } while (0)

#define RENORM() do { \
    float aA[7], aB[7]; \
    _Pragma("unroll") for (int j = 0; j < 7; j++) UPK(p[j], aA[j], aB[j]); \
    float mxA = aA[0], mxB = aB[0]; \
    _Pragma("unroll") for (int j = 1; j < 7; j++) { mxA = fmaxf(mxA, aA[j]); mxB = fmaxf(mxB, aB[j]); } \
    int exA = (__float_as_int(mxA) >> 23) & 0xFF; \
    int exB = (__float_as_int(mxB) >> 23) & 0xFF; \
    float invA = __int_as_float((254 - exA) << 23); \
    float invB = __int_as_float((254 - exB) << 23); \
    xsA += exA - 127; xsB += exB - 127; \
    u64 iv = PK(invA, invB); \
    _Pragma("unroll") for (int j = 0; j < 7; j++) p[j] = MUL2(p[j], iv); } while (0)

// ===================== FORWARD role: t in [0,256) =====================
static __device__ __noinline__ void fwd_role(
    const float* __restrict__ em, const int* __restrict__ labels,
    const int* __restrict__ mask, const float* __restrict__ startT,
    const float* __restrict__ trans,
    float* ES, int* MS, int* LS, const float* STRs,
    int group, int lane)
{
    const int seqA = group * 64 + lane;
    const int seqB = seqA + 32;
    const float* emb  = em + (size_t)(group * 64) * (Tv * 7);
    const int*   labb = labels + (size_t)(group * 64) * Tv;
    const int*   mskb = mask   + (size_t)(group * 64) * Tv;

    u64 EE[7][7];
#pragma unroll
    for (int i = 0; i < 7; i++)
#pragma unroll
        for (int j = 0; j < 7; j++) {
            float e = __expf(__ldg(&trans[i * 7 + j]));
            EE[i][j] = PK(e, e);
        }

    u64 p[7];
    int xsA = 0, xsB = 0;
    float numA = 0.f, numB = 0.f;
    int cntA = 0, cntB = 0;

    auto FSTEP = [&](const float* eA, const float* eB) {
        u64 q[7];
#pragma unroll
        for (int j = 0; j < 7; j++) q[j] = MUL2(p[0], EE[0][j]);
#pragma unroll
        for (int i = 1; i < 7; i++)
#pragma unroll
            for (int j = 0; j < 7; j++) q[j] = FMA2(p[i], EE[i][j], q[j]);
#pragma unroll
        for (int j = 0; j < 7; j++)
            p[j] = MUL2(q[j], PK(__expf(eA[j]), __expf(eB[j])));
    };
    auto SSTEP = [&](const float* eA, const float* eB, int MA, int MB) {
        u64 q[7];
#pragma unroll
        for (int j = 0; j < 7; j++) q[j] = MUL2(p[0], EE[0][j]);
#pragma unroll
        for (int i = 1; i < 7; i++)
#pragma unroll
            for (int j = 0; j < 7; j++) q[j] = FMA2(p[i], EE[i][j], q[j]);
#pragma unroll
        for (int j = 0; j < 7; j++)
            q[j] = MUL2(q[j], PK(__expf(eA[j]), __expf(eB[j])));
        u64 mm = ((u64)(MB ? 0xFFFFFFFFu : 0u) << 32) | (MA ? 0xFFFFFFFFu : 0u);
#pragma unroll
        for (int j = 0; j < 7; j++) p[j] = (q[j] & mm) | (p[j] & ~mm);
    };

    STAGE(0, 0); STAGE(1, 1); STAGE(2, 2);
    CP_WAIT2(); __syncwarp();

    int carryA = 0, carryB = 0;
#pragma unroll 1
    for (int m = 0; m < 32; m++) {
        if (m > 0) { CP_WAIT2(); __syncwarp(); }
        int st = m % 3;
        const float* rA = ES + st * EFLOATS + lane * ROWW;
        const float* rB = rA + 32 * ROWW;
        const int* mrA = MS + st * MINTS + lane * MROWW;
        const int* mrB = mrA + 32 * MROWW;
        const int* lrA = LS + st * MINTS + lane * MROWW;
        const int* lrB = lrA + 32 * MROWW;

        int4 xa0 = *(const int4*)(mrA), xa1 = *(const int4*)(mrA + 4);
        int4 xb0 = *(const int4*)(mrB), xb1 = *(const int4*)(mrB + 4);
        int am = xa0.x&xa0.y&xa0.z&xa0.w&xa1.x&xa1.y&xa1.z&xa1.w
               & xb0.x&xb0.y&xb0.z&xb0.w&xb1.x&xb1.y&xb1.z&xb1.w;
        int fast = __all_sync(0xFFFFFFFFu, am);

        // ---- numerator (chain-free, carried adjacent labels) ----
        int PA = carryA, PB = carryB;
#pragma unroll
        for (int s = 0; s < 8; s++) {
            int LA = lrA[s]; LA = LA < 0 ? 0 : LA;
            int LB = lrB[s]; LB = LB < 0 ? 0 : LB;
            if (m == 0 && s == 0) {
                numA = __ldg(startT + LA) + rA[LA];  cntA++;
                numB = __ldg(startT + LB) + rB[LB];  cntB++;
            } else if (fast) {
                numA += STRs[PA * 7 + LA] + rA[s * 7 + LA];  cntA++;
                numB += STRs[PB * 7 + LB] + rB[s * 7 + LB];  cntB++;
            } else {
                int MA = mrA[s], MB = mrB[s];
                float vA = STRs[PA * 7 + LA] + rA[s * 7 + LA];
                float vB = STRs[PB * 7 + LB] + rB[s * 7 + LB];
                numA += MA ? vA : 0.f;  cntA += MA ? 1 : 0;
                numB += MB ? vB : 0.f;  cntB += MB ? 1 : 0;
            }
            PA = LA; PB = LB;
        }
        carryA = PA; carryB = PB;

        // ---- recursion ----
        if (m == 0) {
            float qA[7], qB[7];
#pragma unroll
            for (int j = 0; j < 7; j++) {
                float s0 = __ldg(startT + j);
                qA[j] = __expf(s0 + rA[j]);
                qB[j] = __expf(s0 + rB[j]);
            }
            float mxA = qA[0], mxB = qB[0];
#pragma unroll
            for (int j = 1; j < 7; j++) { mxA = fmaxf(mxA, qA[j]); mxB = fmaxf(mxB, qB[j]); }
            int exA = (__float_as_int(mxA) >> 23) & 0xFF;
            int exB = (__float_as_int(mxB) >> 23) & 0xFF;
            float invA = __int_as_float((254 - exA) << 23);
            float invB = __int_as_float((254 - exB) << 23);
            xsA = exA - 127; xsB = exB - 127;
#pragma unroll
            for (int j = 0; j < 7; j++) p[j] = PK(qA[j] * invA, qB[j] * invB);
#pragma unroll
            for (int s = 1; s < 8; s++) SSTEP(rA + s * 7, rB + s * 7, mrA[s], mrB[s]);
        } else if (fast) {
#pragma unroll
            for (int s = 0; s < 8; s++) FSTEP(rA + s * 7, rB + s * 7);
        } else {
#pragma unroll
            for (int s = 0; s < 8; s++) SSTEP(rA + s * 7, rB + s * 7, mrA[s], mrB[s]);
        }
        RENORM();
        __syncwarp();
        if (m + 3 < 32) STAGE((m + 3) % 3, m + 3); else CP_COMMIT();
    }

    float aA[7], aB[7];
#pragma unroll
    for (int j = 0; j < 7; j++) UPK(p[j], aA[j], aB[j]);
#pragma unroll
    for (int j = 0; j < 7; j++) { gA[seqA * 8 + j] = aA[j]; gA[seqB * 8 + j] = aB[j]; }
    gXF[seqA] = xsA; gXF[seqB] = xsB;
    gNF[seqA] = numA; gNF[seqB] = numB;
    gCF[seqA] = cntA; gCF[seqB] = cntB;
}

// ===================== BACKWARD role: t in [256,512) =====================
static __device__ __noinline__ void bwd_role(
    const float* __restrict__ em, const int* __restrict__ labels,
    const int* __restrict__ mask, const float* __restrict__ endT,
    const float* __restrict__ trans,
    float* ES, int* MS, int* LS, const float* STRs,
    int group, int lane)
{
    const int seqA = group * 64 + lane;
    const int seqB = seqA + 32;
    const float* emb  = em + (size_t)(group * 64) * (Tv * 7);
    const int*   labb = labels + (size_t)(group * 64) * Tv;
    const int*   mskb = mask   + (size_t)(group * 64) * Tv;

    u64 EE[7][7];
#pragma unroll
    for (int i = 0; i < 7; i++)
#pragma unroll
        for (int j = 0; j < 7; j++) {
            float e = __expf(__ldg(&trans[i * 7 + j]));
            EE[i][j] = PK(e, e);
        }

    u64 p[7];
    int xsA = 0, xsB = 0;
    float numA = 0.f, numB = 0.f;
    int cntA = 0, cntB = 0;

    // single-w interleaved backward step: q[i] = sum_j (p_j*x_j) * EE[i][j]
    auto BFSTEP = [&](const float* eA, const float* eB) {
        u64 w = MUL2(p[0], PK(__expf(eA[0]), __expf(eB[0])));
        u64 q[7];
#pragma unroll
        for (int i = 0; i < 7; i++) q[i] = MUL2(w, EE[i][0]);
#pragma unroll
        for (int j = 1; j < 7; j++) {
            w = MUL2(p[j], PK(__expf(eA[j]), __expf(eB[j])));
#pragma unroll
            for (int i = 0; i < 7; i++) q[i] = FMA2(w, EE[i][j], q[i]);
        }
#pragma unroll
        for (int i = 0; i < 7; i++) p[i] = q[i];
    };
    auto BSSTEP = [&](const float* eA, const float* eB, int MA, int MB) {
        u64 w = MUL2(p[0], PK(__expf(eA[0]), __expf(eB[0])));
        u64 q[7];
#pragma unroll
        for (int i = 0; i < 7; i++) q[i] = MUL2(w, EE[i][0]);
#pragma unroll
        for (int j = 1; j < 7; j++) {
            w = MUL2(p[j], PK(__expf(eA[j]), __expf(eB[j])));
#pragma unroll
            for (int i = 0; i < 7; i++) q[i] = FMA2(w, EE[i][j], q[i]);
        }
        u64 mm = ((u64)(MB ? 0xFFFFFFFFu : 0u) << 32) | (MA ? 0xFFFFFFFFu : 0u);
#pragma unroll
        for (int i = 0; i < 7; i++) p[i] = (q[i] & mm) | (p[i] & ~mm);
    };

    int L255A = __ldg(labb + (size_t)lane * Tv + 255);
    int L255B = __ldg(labb + (size_t)(lane + 32) * Tv + 255);
    L255A = L255A < 0 ? 0 : L255A;
    L255B = L255B < 0 ? 0 : L255B;

#pragma unroll
    for (int j = 0; j < 7; j++) { float e = __expf(__ldg(endT + j)); p[j] = PK(e, e); }

    STAGE(0, 63); STAGE(1, 62); STAGE(2, 61);
    CP_WAIT2(); __syncwarp();

    int pendLA = 0, pendMA = 0, pendLB = 0, pendMB = 0;
#pragma unroll 1
    for (int k = 0; k < 32; k++) {
        if (k > 0) { CP_WAIT2(); __syncwarp(); }
        int st = k % 3;
        const float* rA = ES + st * EFLOATS + lane * ROWW;
        const float* rB = rA + 32 * ROWW;
        const int* mrA = MS + st * MINTS + lane * MROWW;
        const int* mrB = mrA + 32 * MROWW;
        const int* lrA = LS + st * MINTS + lane * MROWW;
        const int* lrB = lrA + 32 * MROWW;

        int4 xa0 = *(const int4*)(mrA), xa1 = *(const int4*)(mrA + 4);
        int4 xb0 = *(const int4*)(mrB), xb1 = *(const int4*)(mrB + 4);
        int am = xa0.x&xa0.y&xa0.z&xa0.w&xa1.x&xa1.y&xa1.z&xa1.w
               & xb0.x&xb0.y&xb0.z&xb0.w&xb1.x&xb1.y&xb1.z&xb1.w;
        int fast = __all_sync(0xFFFFFFFFu, am);

        // ---- numerator for this macro (chain-free) ----
        int L0A = lrA[0]; L0A = L0A < 0 ? 0 : L0A;
        int L0B = lrB[0]; L0B = L0B < 0 ? 0 : L0B;
        int PA = L0A, PB = L0B;
#pragma unroll
        for (int s = 1; s < 8; s++) {
            int LA = lrA[s]; LA = LA < 0 ? 0 : LA;
            int LB = lrB[s]; LB = LB < 0 ? 0 : LB;
            if (fast) {
                numA += STRs[PA * 7 + LA] + rA[s * 7 + LA];  cntA++;
                numB += STRs[PB * 7 + LB] + rB[s * 7 + LB];  cntB++;
            } else {
                int MA = mrA[s], MB = mrB[s];
                float vA = STRs[PA * 7 + LA] + rA[s * 7 + LA];
                float vB = STRs[PB * 7 + LB] + rB[s * 7 + LB];
                numA += MA ? vA : 0.f;  cntA += MA ? 1 : 0;
                numB += MB ? vB : 0.f;  cntB += MB ? 1 : 0;
            }
            PA = LA; PB = LB;
        }
        numA += pendMA ? STRs[PA * 7 + pendLA] : 0.f;
        numB += pendMB ? STRs[PB * 7 + pendLB] : 0.f;
        {
            int M0A = fast ? 1 : mrA[0];
            int M0B = fast ? 1 : mrB[0];
            numA += M0A ? rA[L0A] : 0.f;  cntA += M0A ? 1 : 0;
            numB += M0B ? rB[L0B] : 0.f;  cntB += M0B ? 1 : 0;
            pendLA = L0A; pendMA = M0A;
            pendLB = L0B; pendMB = M0B;
        }

        // ---- recursion (descending time) ----
        if (fast) {
#pragma unroll
            for (int s = 7; s >= 0; s--) BFSTEP(rA + s * 7, rB + s * 7);
        } else {
#pragma unroll
            for (int s = 7; s >= 0; s--) BSSTEP(rA + s * 7, rB + s * 7, mrA[s], mrB[s]);
        }
        RENORM();
        __syncwarp();
        if (k + 3 < 32) STAGE((k + 3) % 3, 63 - (k + 3)); else CP_COMMIT();
    }

    numA += pendMA ? STRs[L255A * 7 + pendLA] : 0.f;
    numB += pendMB ? STRs[L255B * 7 + pendLB] : 0.f;

    float aA[7], aB[7];
#pragma unroll
    for (int j = 0; j < 7; j++) UPK(p[j], aA[j], aB[j]);
#pragma unroll
    for (int j = 0; j < 7; j++) { gU[seqA * 8 + j] = aA[j]; gU[seqB * 8 + j] = aB[j]; }
    gXB[seqA] = xsA; gXB[seqB] = xsB;
    gNB[seqA] = numA; gNB[seqB] = numB;
    gCB[seqA] = cntA; gCB[seqB] = cntB;
}

__global__ void __launch_bounds__(32, 1)
crf_half_kernel(const float* __restrict__ em,
                const int* __restrict__ labels,
                const int* __restrict__ mask,
                const float* __restrict__ startT,
                const float* __restrict__ endT,
                const float* __restrict__ trans)
{
    __shared__ float ES[3 * EFLOATS];
    __shared__ int   MS[3 * MINTS];
    __shared__ int   LS[3 * MINTS];
    __shared__ float STRs[49];

    const int lane  = threadIdx.x;
    const int half  = blockIdx.x >> 7;
    const int group = blockIdx.x & 127;

    for (int i = lane; i < 49; i += 32) STRs[i] = trans[i];
    __syncwarp();

    if (half == 0)
        fwd_role(em, labels, mask, startT, trans, ES, MS, LS, STRs, group, lane);
    else
        bwd_role(em, labels, mask, endT, trans, ES, MS, LS, STRs, group, lane);
}

__global__ void __launch_bounds__(256)
combine_kernel(const int* __restrict__ labels,
               const float* __restrict__ endT,
               float* __restrict__ out)
{
    const int seq = blockIdx.x * 256 + threadIdx.x;
    float acc = 0.f;
#pragma unroll
    for (int j = 0; j < 7; j++) acc = fmaf(gA[seq * 8 + j], gU[seq * 8 + j], acc);
    float den = __logf(acc) + (float)(gXF[seq] + gXB[seq]) * 0.69314718055994531f;

    int c = gCF[seq] + gCB[seq];
    int li = c > 0 ? c - 1 : 0;
    int lt = __ldg(labels + (size_t)seq * Tv + li);
    lt = lt < 0 ? 0 : lt;
    float num = gNF[seq] + gNB[seq] + __ldg(endT + lt);

    float v = den - num;
#pragma unroll
    for (int off = 16; off > 0; off >>= 1)
        v += __shfl_xor_sync(0xFFFFFFFFu, v, off);
    if ((threadIdx.x & 31) == 0) atomicAdd(out, v);
}

extern "C" void kernel_launch(void* const* d_in, const int* in_sizes, int n_in,
                              void* d_out, int out_size)
{
    const float* em     = (const float*)d_in[0];
    const int*   labels = (const int*)  d_in[1];
    const int*   mask   = (const int*)  d_in[2];
    const float* startT = (const float*)d_in[3];
    const float* endT   = (const float*)d_in[4];
    const float* trans  = (const float*)d_in[5];

    cudaMemsetAsync(d_out, 0, sizeof(float));
    crf_half_kernel<<<256, 32>>>(em, labels, mask, startT, endT, trans);
    combine_kernel<<<32, 256>>>(labels, endT, (float*)d_out);
}

// round 16
// speedup vs baseline: 1.8574x; 1.8574x over previous
#include <cuda_runtime.h>

#define Tv 512
#define ROWW 60
#define MROWW 12
#define ESTG (32 * ROWW)     // floats per emission stage (one direction)
#define LSTG (32 * MROWW)    // ints per lab/mask stage

// byte offsets in dynamic smem
#define OB_EF 0
#define OB_EB (OB_EF + 3 * ESTG * 4)
#define OB_LF (OB_EB + 3 * ESTG * 4)
#define OB_MF (OB_LF + 3 * LSTG * 4)
#define OB_LB (OB_MF + 3 * LSTG * 4)
#define OB_MB (OB_LB + 3 * LSTG * 4)
#define OB_ST (OB_MB + 3 * LSTG * 4)
#define SMEM_BYTES (OB_ST + 256)

typedef unsigned long long u64;

static __device__ __forceinline__ u64 PK(float a, float b) {
    u64 r; asm("mov.b64 %0,{%1,%2};" : "=l"(r) : "r"(__float_as_uint(a)), "r"(__float_as_uint(b))); return r;
}
static __device__ __forceinline__ void UPK(u64 v, float& a, float& b) {
    unsigned x, y; asm("mov.b64 {%0,%1},%2;" : "=r"(x), "=r"(y) : "l"(v));
    a = __uint_as_float(x); b = __uint_as_float(y);
}
static __device__ __forceinline__ u64 FMA2(u64 a, u64 b, u64 c) {
    u64 d; asm("fma.rn.f32x2 %0,%1,%2,%3;" : "=l"(d) : "l"(a), "l"(b), "l"(c)); return d;
}
static __device__ __forceinline__ u64 MUL2(u64 a, u64 b) {
    u64 d; asm("mul.rn.f32x2 %0,%1,%2;" : "=l"(d) : "l"(a), "l"(b)); return d;
}
static __device__ __forceinline__ void cpa16(void* dst, const void* src) {
    unsigned d = (unsigned)__cvta_generic_to_shared(dst);
    asm volatile("cp.async.cg.shared.global [%0], [%1], 16;" :: "r"(d), "l"(src));
}
#define CP_COMMIT() asm volatile("cp.async.commit_group;")
#define CP_WAIT2()  asm volatile("cp.async.wait_group 2;")

__global__ void __launch_bounds__(32, 1)
crf_fused_kernel(const float* __restrict__ em,
                 const int* __restrict__ labels,
                 const int* __restrict__ mask,
                 const float* __restrict__ startT,
                 const float* __restrict__ endT,
                 const float* __restrict__ trans,
                 float* __restrict__ out)
{
    extern __shared__ char sb[];
    float* EF = (float*)(sb + OB_EF);
    float* EB = (float*)(sb + OB_EB);
    int*   LF = (int*)(sb + OB_LF);
    int*   MF = (int*)(sb + OB_MF);
    int*   LB = (int*)(sb + OB_LB);
    int*   MB = (int*)(sb + OB_MB);
    float* STRs = (float*)(sb + OB_ST);

    const int lane  = threadIdx.x;
    const int group = blockIdx.x;
    const int seq   = group * 32 + lane;

    const float* emb  = em + (size_t)(group * 32) * (Tv * 7);
    const int*   labb = labels + (size_t)(group * 32) * Tv;
    const int*   mskb = mask   + (size_t)(group * 32) * Tv;

    for (int i = lane; i < 49; i += 32) STRs[i] = trans[i];
    __syncwarp();

    // EE2[i][k] = (E[i][k], E[k][i]) : slot0 fwd (E^T.v form), slot1 bwd (E.v form)
    u64 EE2[7][7];
#pragma unroll
    for (int i = 0; i < 7; i++)
#pragma unroll
        for (int k = 0; k < 7; k++) {
            float elo = __expf(__ldg(&trans[i * 7 + k]));
            float ehi = __expf(__ldg(&trans[k * 7 + i]));
            EE2[i][k] = PK(elo, ehi);
        }

    // stage unified macro M: front times 8M..8M+7, back times 8(63-M)..8(63-M)+7
#define STAGEU(SLOT, M) do { \
    int bm = 63 - (M); \
    float* ef = EF + (SLOT) * ESTG;  float* eb = EB + (SLOT) * ESTG; \
    int* lf = LF + (SLOT) * LSTG;    int* mf = MF + (SLOT) * LSTG; \
    int* lb = LB + (SLOT) * LSTG;    int* mb = MB + (SLOT) * LSTG; \
    _Pragma("unroll") \
    for (int i = 0; i < 14; i++) { \
        int idx = i * 32 + lane; int r = (idx * 4682) >> 16; int c = idx - r * 14; \
        cpa16(ef + r * ROWW + c * 4, emb + (size_t)r * (Tv * 7) + (M) * 56 + c * 4); \
        cpa16(eb + r * ROWW + c * 4, emb + (size_t)r * (Tv * 7) + bm * 56 + c * 4); \
    } \
    _Pragma("unroll") \
    for (int i = 0; i < 2; i++) { \
        int idx = i * 32 + lane; int s = idx >> 1; int h = idx & 1; \
        cpa16(lf + s * MROWW + h * 4, labb + (size_t)s * Tv + (M) * 8 + h * 4); \
        cpa16(mf + s * MROWW + h * 4, mskb + (size_t)s * Tv + (M) * 8 + h * 4); \
        cpa16(lb + s * MROWW + h * 4, labb + (size_t)s * Tv + bm * 8 + h * 4); \
        cpa16(mb + s * MROWW + h * 4, mskb + (size_t)s * Tv + bm * 8 + h * 4); \
    } \
    CP_COMMIT(); } while (0)

    u64 p[7];                         // (alpha_t , gamma_{511-t}) pairs
    int xsA = 0, xsB = 0;
    float numF = 0.f, numB = 0.f;
    int cntF = 0, cntB = 0;
    int carryF = 0;
    int pendL = 0, pendM = 0;

    // unified fast step: p = (matvec(p)) .* (exp(f), exp(b))
    auto USTEP = [&](const float* f, const float* b) {
        u64 q[7];
#pragma unroll
        for (int k = 0; k < 7; k++) q[k] = MUL2(p[0], EE2[0][k]);
#pragma unroll
        for (int i = 1; i < 7; i++)
#pragma unroll
            for (int k = 0; k < 7; k++) q[k] = FMA2(p[i], EE2[i][k], q[k]);
#pragma unroll
        for (int k = 0; k < 7; k++)
            p[k] = MUL2(q[k], PK(__expf(f[k]), __expf(b[k])));
    };
    // masked variant (never taken on the bench input; mask is all ones)
    auto USTEPM = [&](const float* f, const float* b, int MA, int MB_) {
        u64 q[7];
#pragma unroll
        for (int k = 0; k < 7; k++) q[k] = MUL2(p[0], EE2[0][k]);
#pragma unroll
        for (int i = 1; i < 7; i++)
#pragma unroll
            for (int k = 0; k < 7; k++) q[k] = FMA2(p[i], EE2[i][k], q[k]);
        u64 mm = ((u64)(MB_ ? 0xFFFFFFFFu : 0u) << 32) | (MA ? 0xFFFFFFFFu : 0u);
#pragma unroll
        for (int k = 0; k < 7; k++) {
            u64 v = MUL2(q[k], PK(__expf(f[k]), __expf(b[k])));
            p[k] = (v & mm) | (p[k] & ~mm);
        }
    };

#define RENORM() do { \
    float aA[7], aB[7]; \
    _Pragma("unroll") for (int j = 0; j < 7; j++) UPK(p[j], aA[j], aB[j]); \
    float mxA = aA[0], mxB = aB[0]; \
    _Pragma("unroll") for (int j = 1; j < 7; j++) { mxA = fmaxf(mxA, aA[j]); mxB = fmaxf(mxB, aB[j]); } \
    int exA = (__float_as_int(mxA) >> 23) & 0xFF; \
    int exB = (__float_as_int(mxB) >> 23) & 0xFF; \
    float invA = __int_as_float((254 - exA) << 23); \
    float invB = __int_as_float((254 - exB) << 23); \
    xsA += exA - 127; xsB += exB - 127; \
    u64 iv = PK(invA, invB); \
    _Pragma("unroll") for (int j = 0; j < 7; j++) p[j] = MUL2(p[j], iv); } while (0)

    // ---- prologue: stage macros 0..2 ----
    STAGEU(0, 0); STAGEU(1, 1); STAGEU(2, 2);
    CP_WAIT2(); __syncwarp();

    // =========== macro 0 (peeled, scalar both directions) ===========
    {
        const float* f = EF + lane * ROWW;
        const float* b = EB + lane * ROWW;       // back times 504..511 (rows 0..7)
        const int* lf = LF + lane * MROWW;
        const int* mf = MF + lane * MROWW;
        const int* lb = LB + lane * MROWW;
        const int* mb = MB + lane * MROWW;

        // ---- forward scalar: init t=0 then masked steps t=1..7 ----
        float aA[7];
#pragma unroll
        for (int j = 0; j < 7; j++) aA[j] = __expf(__ldg(startT + j) + f[j]);
        {   // scalar renorm of aA
            float mx = aA[0];
#pragma unroll
            for (int j = 1; j < 7; j++) mx = fmaxf(mx, aA[j]);
            int ex = (__float_as_int(mx) >> 23) & 0xFF;
            float inv = __int_as_float((254 - ex) << 23);
            xsA += ex - 127;
#pragma unroll
            for (int j = 0; j < 7; j++) aA[j] *= inv;
        }
        int L0 = lf[0]; L0 = L0 < 0 ? 0 : L0;
        numF = __ldg(startT + L0) + f[L0];  cntF++;
        int PA = L0;
#pragma unroll
        for (int s = 1; s < 8; s++) {
            int L = lf[s]; L = L < 0 ? 0 : L;
            int M = mf[s];
            float v = STRs[PA * 7 + L] + f[s * 7 + L];
            numF += M ? v : 0.f;  cntF += M ? 1 : 0;
            PA = L;
            float qv[7];
#pragma unroll
            for (int k = 0; k < 7; k++) {
                float lo, hi; UPK(EE2[0][k], lo, hi);
                qv[k] = aA[0] * lo;
            }
#pragma unroll
            for (int i = 1; i < 7; i++)
#pragma unroll
                for (int k = 0; k < 7; k++) {
                    float lo, hi; UPK(EE2[i][k], lo, hi);
                    qv[k] = fmaf(aA[i], lo, qv[k]);
                }
#pragma unroll
            for (int k = 0; k < 7; k++) {
                float v2 = qv[k] * __expf(f[s * 7 + k]);
                aA[k] = M ? v2 : aA[k];
            }
        }
        carryF = PA;

        // ---- backward scalar (beta domain): times 511..505, then gamma pack with x_504 ----
        float bB[7];
#pragma unroll
        for (int j = 0; j < 7; j++) bB[j] = __expf(__ldg(endT + j));
#pragma unroll
        for (int s = 7; s >= 1; s--) {          // applying time 504+s
            int M = mb[s];
            float w[7];
#pragma unroll
            for (int j = 0; j < 7; j++) w[j] = bB[j] * __expf(b[s * 7 + j]);
            float qv[7];
#pragma unroll
            for (int i = 0; i < 7; i++) {
                float lo, hi; UPK(EE2[i][0], lo, hi);
                qv[i] = w[0] * lo;
            }
#pragma unroll
            for (int j = 1; j < 7; j++)
#pragma unroll
                for (int i = 0; i < 7; i++) {
                    float lo, hi; UPK(EE2[i][j], lo, hi);
                    qv[i] = fmaf(w[j], lo, qv[i]);
                }
#pragma unroll
            for (int i = 0; i < 7; i++) bB[i] = M ? qv[i] : bB[i];
        }
        // numerator bwd for this macro (times 505..511 + emit504, pend trans)
        {
            int Lb0 = lb[0]; Lb0 = Lb0 < 0 ? 0 : Lb0;
            int P = Lb0;
#pragma unroll
            for (int s = 1; s < 8; s++) {
                int L = lb[s]; L = L < 0 ? 0 : L;
                int M = mb[s];
                float v = STRs[P * 7 + L] + b[s * 7 + L];
                numB += M ? v : 0.f;  cntB += M ? 1 : 0;
                P = L;
            }
            // (no pending yet)
            int M0 = mb[0];
            numB += M0 ? b[Lb0] : 0.f;  cntB += M0 ? 1 : 0;
            pendL = Lb0; pendM = M0;
        }
        // pack gamma_504 = x_504 .* beta_504 with alpha_7
#pragma unroll
        for (int j = 0; j < 7; j++) p[j] = PK(aA[j], __expf(b[j]) * bB[j]);
        RENORM();
    }
    __syncwarp();
    STAGEU(0, 3);

    // =========== macros 1..31 ===========
#pragma unroll 1
    for (int m = 1; m < 32; m++) {
        CP_WAIT2(); __syncwarp();
        int st = m % 3;
        const float* f = EF + st * ESTG + lane * ROWW;
        const float* b = EB + st * ESTG + lane * ROWW;
        const int* lf = LF + st * LSTG + lane * MROWW;
        const int* mf = MF + st * LSTG + lane * MROWW;
        const int* lb = LB + st * LSTG + lane * MROWW;
        const int* mb = MB + st * LSTG + lane * MROWW;

        int4 a0 = *(const int4*)(mf), a1 = *(const int4*)(mf + 4);
        int4 b0 = *(const int4*)(mb), b1 = *(const int4*)(mb + 4);
        int am = a0.x&a0.y&a0.z&a0.w&a1.x&a1.y&a1.z&a1.w
               & b0.x&b0.y&b0.z&b0.w&b1.x&b1.y&b1.z&b1.w;
        int fast = __all_sync(0xFFFFFFFFu, am);

        // ---- numerator fwd (times 8m..8m+7) ----
        int PA = carryF;
#pragma unroll
        for (int s = 0; s < 8; s++) {
            int L = lf[s]; L = L < 0 ? 0 : L;
            if (fast) {
                numF += STRs[PA * 7 + L] + f[s * 7 + L];  cntF++;
            } else {
                int M = mf[s];
                float v = STRs[PA * 7 + L] + f[s * 7 + L];
                numF += M ? v : 0.f;  cntF += M ? 1 : 0;
            }
            PA = L;
        }
        carryF = PA;

        // ---- numerator bwd (times 8(63-m)..8(63-m)+7) ----
        {
            int Lb0 = lb[0]; Lb0 = Lb0 < 0 ? 0 : Lb0;
            int P = Lb0;
#pragma unroll
            for (int s = 1; s < 8; s++) {
                int L = lb[s]; L = L < 0 ? 0 : L;
                if (fast) {
                    numB += STRs[P * 7 + L] + b[s * 7 + L];  cntB++;
                } else {
                    int M = mb[s];
                    float v = STRs[P * 7 + L] + b[s * 7 + L];
                    numB += M ? v : 0.f;  cntB += M ? 1 : 0;
                }
                P = L;
            }
            numB += pendM ? STRs[P * 7 + pendL] : 0.f;
            int M0 = fast ? 1 : mb[0];
            numB += M0 ? b[Lb0] : 0.f;  cntB += M0 ? 1 : 0;
            pendL = Lb0; pendM = M0;
        }

        // ---- recursion: step s consumes front row s, back row 7-s ----
        if (fast) {
#pragma unroll
            for (int s = 0; s < 8; s++) USTEP(f + s * 7, b + (7 - s) * 7);
        } else {
#pragma unroll
            for (int s = 0; s < 8; s++) USTEPM(f + s * 7, b + (7 - s) * 7, mf[s], mb[7 - s]);
        }
        RENORM();
        __syncwarp();
        if (m + 3 < 32) STAGEU((m + 3) % 3, m + 3); else CP_COMMIT();
    }

    // =========== epilogue (all in-thread) ===========
    // beta_255 = E * gamma_256 : final matvec, slot1 of q
    u64 q[7];
#pragma unroll
    for (int k = 0; k < 7; k++) q[k] = MUL2(p[0], EE2[0][k]);
#pragma unroll
    for (int i = 1; i < 7; i++)
#pragma unroll
        for (int k = 0; k < 7; k++) q[k] = FMA2(p[i], EE2[i][k], q[k]);

    float acc = 0.f;
#pragma unroll
    for (int j = 0; j < 7; j++) {
        float al, gdum, bdum, be;
        UPK(p[j], al, gdum);     // slot0 = alpha_255
        UPK(q[j], bdum, be);     // slot1 = beta_255
        acc = fmaf(al, be, acc);
    }
    const float LN2 = 0.69314718055994531f;
    float den = __logf(acc) + (float)(xsA + xsB) * LN2;

    // close boundary trans term: trans[l_255, l_256]
    numB += pendM ? STRs[carryF * 7 + pendL] : 0.f;

    int cnt = cntF + cntB;
    int li = cnt > 0 ? cnt - 1 : 0;
    int lt = __ldg(labb + (size_t)lane * Tv + li);
    lt = lt < 0 ? 0 : lt;
    float num = numF + numB + __ldg(endT + lt);

    float v = den - num;
#pragma unroll
    for (int off = 16; off > 0; off >>= 1)
        v += __shfl_xor_sync(0xFFFFFFFFu, v, off);
    if (lane == 0) atomicAdd(out, v);

#undef STAGEU
#undef RENORM
}

extern "C" void kernel_launch(void* const* d_in, const int* in_sizes, int n_in,
                              void* d_out, int out_size)
{
    const float* em     = (const float*)d_in[0];
    const int*   labels = (const int*)  d_in[1];
    const int*   mask   = (const int*)  d_in[2];
    const float* startT = (const float*)d_in[3];
    const float* endT   = (const float*)d_in[4];
    const float* trans  = (const float*)d_in[5];

    cudaFuncSetAttribute(crf_fused_kernel, cudaFuncAttributeMaxDynamicSharedMemorySize, SMEM_BYTES);
    cudaMemsetAsync(d_out, 0, sizeof(float));
    crf_fused_kernel<<<256, 32, SMEM_BYTES>>>(em, labels, mask, startT, endT, trans, (float*)d_out);
}

// round 17
// speedup vs baseline: 2.0211x; 1.0882x over previous
#include <cuda_runtime.h>

#define Tv 512
#define ROWW 60                 // 56 data + 4 pad floats per seq row (240B)
#define MROWW 12                // 8 mask ints + 4 pad
#define ESTG (32 * ROWW)
#define MSTG (32 * MROWW)

__device__ float gA[8192 * 8];
__device__ float gU[8192 * 8];
__device__ int   gXF[8192], gXB[8192];
__device__ float gNF[8192], gNB[8192];
__device__ int   gCF[8192], gCB[8192];
__device__ int   gFlag[256];

static __device__ __forceinline__ void cpa16(void* dst, const void* src) {
    unsigned d = (unsigned)__cvta_generic_to_shared(dst);
    asm volatile("cp.async.cg.shared.global [%0], [%1], 16;" :: "r"(d), "l"(src));
}
#define CP_COMMIT() asm volatile("cp.async.commit_group;")
#define CP_WAIT2()  asm volatile("cp.async.wait_group 2;")

__global__ void __launch_bounds__(64, 1)
crf_half_kernel(const float* __restrict__ em,
                const int* __restrict__ labels,
                const int* __restrict__ mask,
                const float* __restrict__ startT,
                const float* __restrict__ endT,
                const float* __restrict__ trans,
                float* __restrict__ out)
{
    __shared__ float ES[3 * ESTG];
    __shared__ int   MS[3 * MSTG];
    __shared__ float STRs[49];

    const int tid   = threadIdx.x;
    const int wid   = tid >> 5;
    const int lane  = tid & 31;
    const int half  = blockIdx.x >> 8;        // 0 = forward, 1 = backward
    const int group = blockIdx.x & 255;
    const int seq   = group * 32 + lane;

    const float* emb  = em + (size_t)(group * 32) * (Tv * 7);
    const int*   labb = labels + (size_t)(group * 32) * Tv;
    const int*   mskb = mask   + (size_t)(group * 32) * Tv;
    const int4*  lb4  = (const int4*)(labb + (size_t)lane * Tv);

    for (int i = tid; i < 49; i += 64) STRs[i] = trans[i];

    // physical macro for logical step k
#define PMAC(K) (half == 0 ? (K) : 63 - (K))

    // ---- warp1: stage emissions + masks for physical macro PM into SLOT ----
#define STAGE(SLOT, PM) do { \
    float* _eb = ES + (SLOT) * ESTG; \
    int*   _mb = MS + (SLOT) * MSTG; \
    _Pragma("unroll") \
    for (int i = 0; i < 14; i++) { \
        int idx = i * 32 + lane; int r = (idx * 4682) >> 16; int c = idx - r * 14; \
        cpa16(_eb + r * ROWW + c * 4, emb + (size_t)r * (Tv * 7) + (PM) * 56 + c * 4); \
    } \
    _Pragma("unroll") \
    for (int i = 0; i < 2; i++) { \
        int idx = i * 32 + lane; int s = idx >> 1; int h = idx & 1; \
        cpa16(_mb + s * MROWW + h * 4, mskb + (size_t)s * Tv + (PM) * 8 + h * 4); \
    } } while (0)

    // warp0 state
    float E[7][7];
    float st[7];
    int xs = 0;
    // warp1 state
    float num = 0.f;
    int cnt = 0;
    int carryF = 0;           // fwd numerator carry
    int pendL = 0, pendM = 0; // bwd numerator pending
    int4 lc0, lc1;

    if (wid == 0) {
#pragma unroll
        for (int i = 0; i < 7; i++)
#pragma unroll
            for (int j = 0; j < 7; j++)
                E[i][j] = __expf(__ldg(&trans[i * 7 + j]));
        if (half == 1) {
#pragma unroll
            for (int j = 0; j < 7; j++) st[j] = __expf(__ldg(endT + j));
        }
    } else {
        // prologue staging: logical macros 0,1
        STAGE(0, PMAC(0)); CP_COMMIT();
        STAGE(1, PMAC(1)); CP_COMMIT();
        lc0 = __ldg(lb4 + 2 * PMAC(0));
        lc1 = __ldg(lb4 + 2 * PMAC(0) + 1);
    }

#define RENORM() do { \
    float mx = st[0]; \
    _Pragma("unroll") for (int j = 1; j < 7; j++) mx = fmaxf(mx, st[j]); \
    int ex = (__float_as_int(mx) >> 23) & 0xFF; \
    float inv = __int_as_float((254 - ex) << 23); \
    xs += ex - 127; \
    _Pragma("unroll") for (int j = 0; j < 7; j++) st[j] *= inv; } while (0)

#define LOADG(ROWP, G, XE) do { \
    const float4* _q4 = (const float4*)((ROWP) + (G) * 28); \
    _Pragma("unroll") \
    for (int c = 0; c < 7; c++) { \
        float4 _v = _q4[c]; \
        XE[4*c+0] = _v.x; XE[4*c+1] = _v.y; XE[4*c+2] = _v.z; XE[4*c+3] = _v.w; \
    } \
    _Pragma("unroll") \
    for (int k = 0; k < 28; k++) XE[k] = __expf(XE[k]); } while (0)

    // fwd fast/masked steps (pre-exp'd x)
    auto FSTX = [&](const float* x) {
        float q[7];
#pragma unroll
        for (int j = 0; j < 7; j++) q[j] = st[0] * E[0][j];
#pragma unroll
        for (int i = 1; i < 7; i++)
#pragma unroll
            for (int j = 0; j < 7; j++) q[j] = fmaf(st[i], E[i][j], q[j]);
#pragma unroll
        for (int j = 0; j < 7; j++) st[j] = q[j] * x[j];
    };
    auto SSTX = [&](const float* x, int M) {
        float q[7];
#pragma unroll
        for (int j = 0; j < 7; j++) q[j] = st[0] * E[0][j];
#pragma unroll
        for (int i = 1; i < 7; i++)
#pragma unroll
            for (int j = 0; j < 7; j++) q[j] = fmaf(st[i], E[i][j], q[j]);
#pragma unroll
        for (int j = 0; j < 7; j++) {
            float v = q[j] * x[j];
            st[j] = M ? v : st[j];
        }
    };
    // bwd fast/masked steps
    auto BFSTX = [&](const float* x) {
        float w[7];
#pragma unroll
        for (int j = 0; j < 7; j++) w[j] = st[j] * x[j];
        float q[7];
#pragma unroll
        for (int i = 0; i < 7; i++) q[i] = w[0] * E[i][0];
#pragma unroll
        for (int j = 1; j < 7; j++)
#pragma unroll
            for (int i = 0; i < 7; i++) q[i] = fmaf(w[j], E[i][j], q[i]);
#pragma unroll
        for (int i = 0; i < 7; i++) st[i] = q[i];
    };
    auto BSSTX = [&](const float* x, int M) {
        float w[7];
#pragma unroll
        for (int j = 0; j < 7; j++) w[j] = st[j] * x[j];
        float q[7];
#pragma unroll
        for (int i = 0; i < 7; i++) q[i] = w[0] * E[i][0];
#pragma unroll
        for (int j = 1; j < 7; j++)
#pragma unroll
            for (int i = 0; i < 7; i++) q[i] = fmaf(w[j], E[i][j], q[i]);
#pragma unroll
        for (int i = 0; i < 7; i++) st[i] = M ? q[i] : st[i];
    };

    // ======================= main loop =======================
#pragma unroll 1
    for (int m = 0; m < 32; m++) {
        if (wid == 1) {
            if (m + 2 < 32) STAGE((m + 2) % 3, PMAC(m + 2));
            CP_COMMIT();
            CP_WAIT2();                 // logical macro m landed
        }
        __syncthreads();                // macro m visible to warp0

        int stg = m % 3;
        const float* r = ES + stg * ESTG + lane * ROWW;
        const int*  mr = MS + stg * MSTG + lane * MROWW;

        if (wid == 0) {
            // ---------------- recursion (consume macro m) ----------------
            int4 m0 = *(const int4*)(mr), m1 = *(const int4*)(mr + 4);
            int ma[8] = {m0.x, m0.y, m0.z, m0.w, m1.x, m1.y, m1.z, m1.w};
            int am = ma[0]&ma[1]&ma[2]&ma[3]&ma[4]&ma[5]&ma[6]&ma[7];
            int fast = __all_sync(0xFFFFFFFFu, am);

            if (half == 0) {
                if (m == 0) {
                    // init t=0 + steps 1..7
#pragma unroll
                    for (int j = 0; j < 7; j++) st[j] = __expf(__ldg(startT + j) + r[j]);
                    RENORM();
                    { float xe[28]; LOADG(r, 0, xe);
                      SSTX(xe + 7,  ma[1]); SSTX(xe + 14, ma[2]); SSTX(xe + 21, ma[3]); }
                    { float xe[28]; LOADG(r, 1, xe);
                      SSTX(xe + 0,  ma[4]); SSTX(xe + 7,  ma[5]);
                      SSTX(xe + 14, ma[6]); SSTX(xe + 21, ma[7]); }
                } else if (fast) {
                    { float xe[28]; LOADG(r, 0, xe);
                      FSTX(xe + 0); FSTX(xe + 7); FSTX(xe + 14); FSTX(xe + 21); }
                    { float xe[28]; LOADG(r, 1, xe);
                      FSTX(xe + 0); FSTX(xe + 7); FSTX(xe + 14); FSTX(xe + 21); }
                } else {
                    { float xe[28]; LOADG(r, 0, xe);
                      SSTX(xe + 0,  ma[0]); SSTX(xe + 7,  ma[1]);
                      SSTX(xe + 14, ma[2]); SSTX(xe + 21, ma[3]); }
                    { float xe[28]; LOADG(r, 1, xe);
                      SSTX(xe + 0,  ma[4]); SSTX(xe + 7,  ma[5]);
                      SSTX(xe + 14, ma[6]); SSTX(xe + 21, ma[7]); }
                }
            } else {
                // backward half: descending time within macro
                if (fast) {
                    { float xe[28]; LOADG(r, 1, xe);
                      BFSTX(xe + 21); BFSTX(xe + 14); BFSTX(xe + 7); BFSTX(xe + 0); }
                    { float xe[28]; LOADG(r, 0, xe);
                      BFSTX(xe + 21); BFSTX(xe + 14); BFSTX(xe + 7); BFSTX(xe + 0); }
                } else {
                    { float xe[28]; LOADG(r, 1, xe);
                      BSSTX(xe + 21, ma[7]); BSSTX(xe + 14, ma[6]);
                      BSSTX(xe + 7,  ma[5]); BSSTX(xe + 0,  ma[4]); }
                    { float xe[28]; LOADG(r, 0, xe);
                      BSSTX(xe + 21, ma[3]); BSSTX(xe + 14, ma[2]);
                      BSSTX(xe + 7,  ma[1]); BSSTX(xe + 0,  ma[0]); }
                }
            }
            RENORM();
        } else {
            // ---------------- numerator (warp1, staged data) ----------------
            int4 m0 = *(const int4*)(mr), m1 = *(const int4*)(mr + 4);
            int ma[8] = {m0.x, m0.y, m0.z, m0.w, m1.x, m1.y, m1.z, m1.w};
            int la[8] = {lc0.x, lc0.y, lc0.z, lc0.w, lc1.x, lc1.y, lc1.z, lc1.w};
            if (m < 31) {
                lc0 = __ldg(lb4 + 2 * PMAC(m + 1));
                lc1 = __ldg(lb4 + 2 * PMAC(m + 1) + 1);
            }
            if (half == 0) {
                int P = carryF;
#pragma unroll
                for (int s = 0; s < 8; s++) {
                    int L = la[s]; L = L < 0 ? 0 : L;
                    if (m == 0 && s == 0) {
                        num = __ldg(startT + L) + r[L];  cnt++;
                    } else {
                        float v = STRs[P * 7 + L] + r[s * 7 + L];
                        num += ma[s] ? v : 0.f;  cnt += ma[s] ? 1 : 0;
                    }
                    P = L;
                }
                carryF = P;
            } else {
                int L0 = la[0]; L0 = L0 < 0 ? 0 : L0;
                int P = L0;
#pragma unroll
                for (int s = 1; s < 8; s++) {
                    int L = la[s]; L = L < 0 ? 0 : L;
                    float v = STRs[P * 7 + L] + r[s * 7 + L];
                    num += ma[s] ? v : 0.f;  cnt += ma[s] ? 1 : 0;
                    P = L;
                }
                num += pendM ? STRs[P * 7 + pendL] : 0.f;
                num += ma[0] ? r[L0] : 0.f;  cnt += ma[0] ? 1 : 0;
                pendL = L0; pendM = ma[0];
            }
        }
        __syncthreads();                // slot m%3 free for restage
    }

    // ======================= publish =======================
    if (wid == 0) {
        if (half == 0) {
#pragma unroll
            for (int j = 0; j < 7; j++) gA[seq * 8 + j] = st[j];
            gXF[seq] = xs;
        } else {
#pragma unroll
            for (int j = 0; j < 7; j++) gU[seq * 8 + j] = st[j];
            gXB[seq] = xs;
        }
    } else {
        if (half == 0) { gNF[seq] = num; gCF[seq] = cnt; }
        else {
            // close final pending term against label t=255
            int L255 = __ldg(labb + (size_t)lane * Tv + 255);
            L255 = L255 < 0 ? 0 : L255;
            num += pendM ? STRs[L255 * 7 + pendL] : 0.f;
            gNB[seq] = num; gCB[seq] = cnt;
        }
    }
    __threadfence();
    __syncthreads();

    // ======================= fused combine (second finisher) =======================
    if (wid == 0) {
        int old = 0;
        if (lane == 0) old = atomicAdd(&gFlag[group], 1);
        old = __shfl_sync(0xFFFFFFFFu, old, 0);
        if (old == 1) {
            __threadfence();
            float acc = 0.f;
#pragma unroll
            for (int j = 0; j < 7; j++) acc = fmaf(gA[seq * 8 + j], gU[seq * 8 + j], acc);
            float den = __logf(acc) + (float)(gXF[seq] + gXB[seq]) * 0.69314718055994531f;
            int c = gCF[seq] + gCB[seq];
            int li = c > 0 ? c - 1 : 0;
            int lt = __ldg(labb + (size_t)lane * Tv + li);
            lt = lt < 0 ? 0 : lt;
            float nm = gNF[seq] + gNB[seq] + __ldg(endT + lt);
            float v = den - nm;
#pragma unroll
            for (int off = 16; off > 0; off >>= 1)
                v += __shfl_xor_sync(0xFFFFFFFFu, v, off);
            if (lane == 0) {
                atomicAdd(out, v);
                gFlag[group] = 0;       // reset for next graph replay
            }
        }
    }

#undef STAGE
#undef RENORM
#undef LOADG
#undef PMAC
}

extern "C" void kernel_launch(void* const* d_in, const int* in_sizes, int n_in,
                              void* d_out, int out_size)
{
    const float* em     = (const float*)d_in[0];
    const int*   labels = (const int*)  d_in[1];
    const int*   mask   = (const int*)  d_in[2];
    const float* startT = (const float*)d_in[3];
    const float* endT   = (const float*)d_in[4];
    const float* trans  = (const float*)d_in[5];

    cudaMemsetAsync(d_out, 0, sizeof(float));
    crf_half_kernel<<<512, 64>>>(em, labels, mask, startT, endT, trans, (float*)d_out);
}